// round 1
// baseline (speedup 1.0000x reference)
#include <cuda_runtime.h>
#include <math.h>

#define DEPTH 512
#define NPAIR 255            // pairs 0..254 real; cols 510,511 have zero PE
#define ROWS_PER_BLOCK 128
#define THREADS 128          // thread t -> float4 covering cols 4t..4t+3

__global__ __launch_bounds__(THREADS)
void emb_pe_kernel(const int* __restrict__ idx,
                   const float4* __restrict__ wl4,   // wordlist viewed [VOCAB][128] float4
                   float4* __restrict__ out4,        // out viewed [L][128] float4
                   int L)
{
    __shared__ int sh_idx[ROWS_PER_BLOCK];

    const int t    = threadIdx.x;
    const int row0 = blockIdx.x * ROWS_PER_BLOCK;
    const int nrows = min(ROWS_PER_BLOCK, L - row0);

    // stage idx tile through shared
    for (int r = t; r < nrows; r += THREADS)
        sh_idx[r] = idx[row0 + r];
    __syncthreads();

    // Column pairs owned by this thread
    const int p0 = 2 * t;
    const int p1 = 2 * t + 1;

    // angle(i, j) = i * exp(-ln(10000) * j / 256)
    const double NEG_LN1E4_256 = -9.210340371976184 / 256.0;

    // fp64 init (once per thread): phasor at row0 and per-row rotation step
    double w0 = exp((double)p0 * NEG_LN1E4_256);
    double a0 = (double)row0 * w0;
    float s0 = (float)sin(a0), c0 = (float)cos(a0);
    float sw0 = (float)sin(w0), cw0 = (float)cos(w0);

    float s1, c1, sw1, cw1;
    if (p1 < NPAIR) {
        double w1 = exp((double)p1 * NEG_LN1E4_256);
        double a1 = (double)row0 * w1;
        s1 = (float)sin(a1); c1 = (float)cos(a1);
        sw1 = (float)sin(w1); cw1 = (float)cos(w1);
    } else {
        s1 = 0.0f; c1 = 0.0f; sw1 = 0.0f; cw1 = 1.0f;  // identity rotation keeps (0,0)
    }

    const float4* __restrict__ wbase = wl4;
    size_t out_off = (size_t)row0 * (DEPTH / 4) + t;

    #pragma unroll 4
    for (int r = 0; r < nrows; ++r) {
        int token = sh_idx[r];
        float4 e = __ldg(&wbase[(size_t)token * (DEPTH / 4) + t]);

        float4 o;
        o.x = e.x + s0;
        o.y = e.y + c0;
        o.z = e.z + s1;
        o.w = e.w + c1;
        __stcs(&out4[out_off], o);
        out_off += (DEPTH / 4);

        // rotate phasors by one row step
        float ns0 = fmaf(s0, cw0,  c0 * sw0);
        float nc0 = fmaf(c0, cw0, -s0 * sw0);
        float ns1 = fmaf(s1, cw1,  c1 * sw1);
        float nc1 = fmaf(c1, cw1, -s1 * sw1);
        s0 = ns0; c0 = nc0; s1 = ns1; c1 = nc1;
    }
}

extern "C" void kernel_launch(void* const* d_in, const int* in_sizes, int n_in,
                              void* d_out, int out_size)
{
    const int*   idx = (const int*)d_in[0];
    const float* wl  = (const float*)d_in[1];
    float*       out = (float*)d_out;

    int L = in_sizes[0];
    int blocks = (L + ROWS_PER_BLOCK - 1) / ROWS_PER_BLOCK;

    emb_pe_kernel<<<blocks, THREADS>>>(idx, (const float4*)wl, (float4*)out, L);
}

// round 2
// speedup vs baseline: 1.5577x; 1.5577x over previous
#include <cuda_runtime.h>
#include <math.h>

#define DEPTH     512
#define NPAIR     255          // pairs 0..254 real; cols 510,511 have zero PE
#define ROWS      32           // rows per block
#define THREADS   128          // thread t -> float4 covering cols 4t..4t+3
#define QH_BITS   6            // q = qh*64 + ql, q < 4096 (L <= 131072)
#define QH_N      64
#define QL_N      64

// Phasor tables: .x = sin, .y = cos. Index [q*256 + j], j = pair id (j=255 zeroed).
__device__ float2 g_T1[QH_N * 256];   // phasor(qh * 2048 * w_j)
__device__ float2 g_T2[QL_N * 256];   // phasor(ql * 32   * w_j)
__device__ float2 g_S [256];          // phasor(w_j)  (row step)

// ---------------------------------------------------------------------------
// Init kernel: fills the three tables with fp64-accurate phasors. ~33K entries.
// ---------------------------------------------------------------------------
__global__ void init_tables_kernel()
{
    const int i = blockIdx.x * blockDim.x + threadIdx.x;
    const int N1 = QH_N * 256;
    const int N2 = QL_N * 256;
    const double C = -9.210340371976184 / 256.0;   // -ln(10000)/256

    if (i < N1) {
        int qh = i >> 8, j = i & 255;
        float2 v;
        if (j >= NPAIR) { v.x = 0.0f; v.y = 0.0f; }
        else {
            double w = exp((double)j * C);
            double a = (double)(qh * 2048) * w;
            v.x = (float)sin(a); v.y = (float)cos(a);
        }
        g_T1[i] = v;
    } else if (i < N1 + N2) {
        int k = i - N1;
        int ql = k >> 8, j = k & 255;
        float2 v;
        if (j >= NPAIR) { v.x = 0.0f; v.y = 0.0f; }
        else {
            double w = exp((double)j * C);
            double a = (double)(ql * 32) * w;
            v.x = (float)sin(a); v.y = (float)cos(a);
        }
        g_T2[k] = v;
    } else if (i < N1 + N2 + 256) {
        int j = i - N1 - N2;
        float2 v;
        if (j >= NPAIR) { v.x = 0.0f; v.y = 1.0f; }   // identity rotation
        else {
            double w = exp((double)j * C);
            v.x = (float)sin(w); v.y = (float)cos(w);
        }
        g_S[j] = v;
    }
}

// ---------------------------------------------------------------------------
// Main kernel: one thread per float4 column group, 32 rows per block.
// ---------------------------------------------------------------------------
__global__ __launch_bounds__(THREADS)
void emb_pe_kernel(const int* __restrict__ idx,
                   const float4* __restrict__ wl4,   // wordlist [VOCAB][128] float4
                   float4* __restrict__ out4,        // out      [L][128] float4
                   int L)
{
    __shared__ int sh_idx[ROWS];

    const int t  = threadIdx.x;
    const int q  = blockIdx.x;
    const int row0 = q * ROWS;
    const int nrows = min(ROWS, L - row0);

    if (t < ROWS && t < nrows) sh_idx[t] = idx[row0 + t];
    __syncthreads();

    const int qh = q >> QH_BITS;
    const int ql = q & (QL_N - 1);
    const int p0 = 2 * t;
    const int p1 = 2 * t + 1;

    // base phasor = T1 (x) T2  (complex multiply; sin in .x, cos in .y)
    float2 A0 = g_T1[(qh << 8) + p0], B0 = g_T2[(ql << 8) + p0], S0 = g_S[p0];
    float2 A1 = g_T1[(qh << 8) + p1], B1 = g_T2[(ql << 8) + p1], S1 = g_S[p1];

    float s0 = fmaf(A0.x, B0.y,  A0.y * B0.x);
    float c0 = fmaf(A0.y, B0.y, -A0.x * B0.x);
    float s1 = fmaf(A1.x, B1.y,  A1.y * B1.x);
    float c1 = fmaf(A1.y, B1.y, -A1.x * B1.x);

    size_t out_off = (size_t)row0 * (DEPTH / 4) + t;

    if (nrows == ROWS) {
        #pragma unroll 8
        for (int r = 0; r < ROWS; ++r) {
            int token = sh_idx[r];
            float4 e = __ldg(&wl4[(size_t)token * (DEPTH / 4) + t]);
            float4 o;
            o.x = e.x + s0;
            o.y = e.y + c0;
            o.z = e.z + s1;
            o.w = e.w + c1;
            __stcs(&out4[out_off], o);
            out_off += (DEPTH / 4);

            float ns0 = fmaf(s0, S0.y,  c0 * S0.x);
            float nc0 = fmaf(c0, S0.y, -s0 * S0.x);
            float ns1 = fmaf(s1, S1.y,  c1 * S1.x);
            float nc1 = fmaf(c1, S1.y, -s1 * S1.x);
            s0 = ns0; c0 = nc0; s1 = ns1; c1 = nc1;
        }
    } else {
        for (int r = 0; r < nrows; ++r) {
            int token = sh_idx[r];
            float4 e = __ldg(&wl4[(size_t)token * (DEPTH / 4) + t]);
            float4 o;
            o.x = e.x + s0;
            o.y = e.y + c0;
            o.z = e.z + s1;
            o.w = e.w + c1;
            __stcs(&out4[out_off], o);
            out_off += (DEPTH / 4);

            float ns0 = fmaf(s0, S0.y,  c0 * S0.x);
            float nc0 = fmaf(c0, S0.y, -s0 * S0.x);
            float ns1 = fmaf(s1, S1.y,  c1 * S1.x);
            float nc1 = fmaf(c1, S1.y, -s1 * S1.x);
            s0 = ns0; c0 = nc0; s1 = ns1; c1 = nc1;
        }
    }
}

extern "C" void kernel_launch(void* const* d_in, const int* in_sizes, int n_in,
                              void* d_out, int out_size)
{
    const int*   idx = (const int*)d_in[0];
    const float* wl  = (const float*)d_in[1];
    float*       out = (float*)d_out;

    int L = in_sizes[0];

    int init_total = QH_N * 256 + QL_N * 256 + 256;
    init_tables_kernel<<<(init_total + 255) / 256, 256>>>();

    int blocks = (L + ROWS - 1) / ROWS;
    emb_pe_kernel<<<blocks, THREADS>>>(idx, (const float4*)wl, (float4*)out, L);
}